// round 16
// baseline (speedup 1.0000x reference)
#include <cuda_runtime.h>
#include <cuda_fp16.h>
#include <math.h>
#include <stdint.h>

#define TT   1024
#define SSZ  1024
#define BB   4
#define DD   1024
#define HH   16
#define HDD  64
#define FFND 4096
#define MM   (TT*BB)

// ---------------- scratch (device globals; no allocs allowed) ----------------
__device__ __half   g_state_h[MM*DD];
__device__ __half   g_enc_h[MM*DD];
__device__ __half   g_qkv_h[(size_t)MM*3*DD];   // fused self q|k|v, row stride 3072
__device__ __half   g_kv_h[(size_t)MM*2*DD];    // fused enc k|v, row stride 2048
__device__ __half   g_q2_h[MM*DD];
__device__ __half   g_ctx_h[MM*DD];
__device__ float    g_tmp[MM*DD];
__device__ float    g_x1[MM*DD];
__device__ __half   g_x1h[MM*DD];
__device__ float    g_x2[MM*DD];
__device__ __half   g_x2h[MM*DD];
__device__ __half   g_ffn_h[(size_t)MM*FFND];
__device__ float    g_rs_self[MM];
__device__ float    g_rs_enc[MM];
__device__ __half   g_wh[16*1024*1024];

#define WOFF_SAQ  (0*1048576)
#define WOFF_SAK  (1*1048576)
#define WOFF_SAV  (2*1048576)
#define WOFF_SAO  (3*1048576)
#define WOFF_EAQ  (4*1048576)
#define WOFF_EAK  (5*1048576)
#define WOFF_EAV  (6*1048576)
#define WOFF_EAO  (7*1048576)
#define WOFF_FC1  (8*1048576)
#define WOFF_FC2  (12*1048576)

struct BiasSet { const float* p[4]; };

// ---------------- helpers ----------------
__device__ __forceinline__ float block_sum(float v) {
    __shared__ float sh[8];
    __shared__ float res;
    int lane = threadIdx.x & 31, w = threadIdx.x >> 5;
    #pragma unroll
    for (int o = 16; o > 0; o >>= 1) v += __shfl_xor_sync(0xffffffffu, v, o);
    __syncthreads();
    if (lane == 0) sh[w] = v;
    __syncthreads();
    if (threadIdx.x == 0) {
        float t = 0.f;
        #pragma unroll
        for (int i = 0; i < 8; i++) t += sh[i];
        res = t;
    }
    __syncthreads();
    return res;
}

__device__ __forceinline__ void mma_fp16(float* d, const uint32_t* a, uint32_t b0, uint32_t b1) {
    asm volatile(
        "mma.sync.aligned.m16n8k16.row.col.f32.f16.f16.f32 "
        "{%0,%1,%2,%3}, {%4,%5,%6,%7}, {%8,%9}, {%0,%1,%2,%3};"
        : "+f"(d[0]), "+f"(d[1]), "+f"(d[2]), "+f"(d[3])
        : "r"(a[0]), "r"(a[1]), "r"(a[2]), "r"(a[3]), "r"(b0), "r"(b1));
}

__device__ __forceinline__ void ldsm_x4(uint32_t& r0, uint32_t& r1, uint32_t& r2, uint32_t& r3,
                                        uint32_t addr) {
    asm volatile("ldmatrix.sync.aligned.m8n8.x4.shared.b16 {%0,%1,%2,%3}, [%4];"
                 : "=r"(r0), "=r"(r1), "=r"(r2), "=r"(r3) : "r"(addr));
}

__global__ void expand_mask_kernel(const int* __restrict__ mask,
                                   float* __restrict__ rowscale, int L) {
    int r = blockIdx.x * blockDim.x + threadIdx.x;
    if (r < L * BB) {
        int pos = r / BB, b = r % BB;
        rowscale[r] = mask[b * L + pos] ? 0.f : 1.f;
    }
}

// ---------------- fused fp32 -> fp16 conversion over 12 segments ----------------
struct CvtJobs {
    const float* src[12];
    __half*      dst[12];
    int          n[12];
};

__global__ __launch_bounds__(256) void cvt_all_kernel(CvtJobs jobs)
{
    int seg = blockIdx.y;
    int n = jobs.n[seg];
    int i = (blockIdx.x * blockDim.x + threadIdx.x) * 4;
    if (i < n) {
        float4 v = *(const float4*)(jobs.src[seg] + i);
        *(__half2*)(jobs.dst[seg] + i)     = __floats2half2_rn(v.x, v.y);
        *(__half2*)(jobs.dst[seg] + i + 2) = __floats2half2_rn(v.z, v.w);
    }
}

// =====================================================================
// FP16 GEMM (mma.m16n8k16 + ldmatrix): C = A @ W^T (+bias set, segmented
// rowscale, relu). CTA 256x128, K-chunk 128 halfs (272B rows, stride-68w).
// 256 thr, 8 warps 4m x 2n, warp 64x64. 2-stage cp.async.
// smem/stage: A 256*68 + B 128*68 = 26112 words; 2 stages = 208896 B.
// =====================================================================
#define RSW 68
#define A_W  (256*RSW)
#define B_W  (128*RSW)
#define STG_W (A_W + B_W)
#define GSMB (2*STG_W*4)

__global__ __launch_bounds__(256) void gemm_fp16_kernel(
    const __half* __restrict__ A, const __half* __restrict__ W,
    BiasSet bias, const float* __restrict__ rowscale, int rsseg,
    float* __restrict__ C, __half* __restrict__ Ct16,
    int M, int N, int K, int relu)
{
    extern __shared__ uint32_t sm[];
    const int tid = threadIdx.x;
    const int lane = tid & 31, warp = tid >> 5;
    const int wm = warp & 3, wn = warp >> 2;
    const int g = lane >> 2, tig = lane & 3;
    const int bx = blockIdx.x, by = blockIdx.y;

    float d[4][8][4];
    #pragma unroll
    for (int mt = 0; mt < 4; mt++)
        #pragma unroll
        for (int nt = 0; nt < 8; nt++)
            #pragma unroll
            for (int i = 0; i < 4; i++) d[mt][nt][i] = 0.f;

    uint32_t smbase = (uint32_t)__cvta_generic_to_shared(sm);
    const __half* Abase = A + (size_t)(by * 256) * K;
    const __half* Wbase = W + (size_t)(bx * 128) * K;

    auto issue = [&](int k0, int stg) {
        uint32_t b = smbase + (uint32_t)stg * (STG_W * 4);
        // A: 256 rows x 16 chunks of 16B -> 16 per thread
        #pragma unroll
        for (int i = 0; i < 16; i++) {
            int f = tid + (i << 8);
            int r = f >> 4, c16 = f & 15;
            uint32_t dst = b + (uint32_t)(r * RSW + c16 * 4) * 4;
            const __half* src = Abase + (size_t)r * K + k0 + c16 * 8;
            asm volatile("cp.async.cg.shared.global [%0], [%1], 16;"
                         :: "r"(dst), "l"(src) : "memory");
        }
        // B: 128 rows x 16 chunks -> 8 per thread
        #pragma unroll
        for (int i = 0; i < 8; i++) {
            int f = tid + (i << 8);
            int r = f >> 4, c16 = f & 15;
            uint32_t dst = b + (uint32_t)(A_W + r * RSW + c16 * 4) * 4;
            const __half* src = Wbase + (size_t)r * K + k0 + c16 * 8;
            asm volatile("cp.async.cg.shared.global [%0], [%1], 16;"
                         :: "r"(dst), "l"(src) : "memory");
        }
        asm volatile("cp.async.commit_group;" ::: "memory");
    };

    // ldmatrix lane offsets (272B row stride)
    const uint32_t laneA = (uint32_t)(((lane & 7) + ((lane >> 3) & 1) * 8) * 272 + (lane >> 4) * 16);
    const uint32_t laneB = (uint32_t)((lane & 7) * 272 + ((lane >> 3) & 1) * 16 + (lane >> 4) * 8 * 272);
    const uint32_t aRowB = (uint32_t)(wm * 64) * 272;
    const uint32_t bRowB = (uint32_t)(A_W * 4) + (uint32_t)(wn * 64) * 272;

    issue(0, 0);
    int stage = 0;
    for (int k0 = 0; k0 < K; k0 += 128) {
        bool nxt = (k0 + 128) < K;
        if (nxt) {
            issue(k0 + 128, stage ^ 1);
            asm volatile("cp.async.wait_group 1;" ::: "memory");
        } else {
            asm volatile("cp.async.wait_group 0;" ::: "memory");
        }
        __syncthreads();

        uint32_t abase = smbase + (uint32_t)stage * (STG_W * 4) + aRowB + laneA;
        uint32_t bbase = smbase + (uint32_t)stage * (STG_W * 4) + bRowB + laneB;
        #pragma unroll
        for (int ks = 0; ks < 8; ks++) {
            uint32_t kof = ks * 32;
            uint32_t af[4][4];
            #pragma unroll
            for (int mt = 0; mt < 4; mt++)
                ldsm_x4(af[mt][0], af[mt][1], af[mt][2], af[mt][3],
                        abase + (uint32_t)(mt * 16) * 272 + kof);
            #pragma unroll
            for (int ntp = 0; ntp < 4; ntp++) {
                uint32_t b00, b01, b10, b11;
                ldsm_x4(b00, b01, b10, b11, bbase + (uint32_t)(ntp * 16) * 272 + kof);
                #pragma unroll
                for (int mt = 0; mt < 4; mt++) {
                    mma_fp16(d[mt][2 * ntp],     af[mt], b00, b01);
                    mma_fp16(d[mt][2 * ntp + 1], af[mt], b10, b11);
                }
            }
        }
        __syncthreads();
        stage ^= 1;
    }

    const float* bp = bias.p[(bx * 128) >> 10];
    const int bcol0 = (bx * 128) & 1023;
    const bool useRs = rowscale && (((bx * 128) >> 10) == rsseg || rsseg < 0);

    #pragma unroll
    for (int mt = 0; mt < 4; mt++) {
        int row0 = by * 256 + wm * 64 + mt * 16 + g;
        float rs0 = useRs ? rowscale[row0] : 1.f;
        float rs1 = useRs ? rowscale[row0 + 8] : 1.f;
        #pragma unroll
        for (int nt = 0; nt < 8; nt++) {
            int coff = wn * 64 + nt * 8 + tig * 2;
            int col = bx * 128 + coff;
            float b0 = bp[bcol0 + coff], b1 = bp[bcol0 + coff + 1];
            float v00 = d[mt][nt][0] * rs0 + b0, v01 = d[mt][nt][1] * rs0 + b1;
            float v10 = d[mt][nt][2] * rs1 + b0, v11 = d[mt][nt][3] * rs1 + b1;
            if (relu) {
                v00 = fmaxf(v00, 0.f); v01 = fmaxf(v01, 0.f);
                v10 = fmaxf(v10, 0.f); v11 = fmaxf(v11, 0.f);
            }
            size_t o0 = (size_t)row0 * N + col;
            size_t o1 = (size_t)(row0 + 8) * N + col;
            if (C) {
                *(float2*)(C + o0) = make_float2(v00, v01);
                *(float2*)(C + o1) = make_float2(v10, v11);
            }
            if (Ct16) {
                *(__half2*)(Ct16 + o0) = __floats2half2_rn(v00, v01);
                *(__half2*)(Ct16 + o1) = __floats2half2_rn(v10, v11);
            }
        }
    }
}

// =====================================================================
// Fused flash attention, fp16 MMA + ldmatrix, strided Q/K/V inputs.
// =====================================================================
#define FQ2 0
#define FK2 4608
#define FV2 9216
#define FP2 13568
#define FL2_WORDS 22272

__global__ __launch_bounds__(256) void flash_fp16_kernel(
    const __half* __restrict__ Q, int qs,
    const __half* __restrict__ Kk, int ks_,
    const __half* __restrict__ V, int vs,
    const float* __restrict__ mask,
    __half* __restrict__ ctx_h, float* __restrict__ attn, int causal)
{
    extern __shared__ uint32_t sm[];
    uint32_t* Qs = sm + FQ2;
    uint32_t* Ks = sm + FK2;
    uint32_t* Vs = sm + FV2;
    const int tid = threadIdx.x;
    const int lane = tid & 31, warp = tid >> 5;
    const int g = lane >> 2, tig = lane & 3;
    const int bh = blockIdx.y;
    const int bb = bh / HH, h = bh % HH;
    const int tb = causal ? ((int)gridDim.x - 1 - (int)blockIdx.x) : (int)blockIdx.x;
    const int t0 = tb * 128;
    const int wr0 = warp * 16;
    uint32_t* Pw = sm + FP2 + warp * 1088;

    uint32_t smbase = (uint32_t)__cvta_generic_to_shared(sm);
    const uint32_t laneA36 = (uint32_t)(((lane & 7) + ((lane >> 3) & 1) * 8) * 144 + (lane >> 4) * 16);
    const uint32_t laneB36 = (uint32_t)((lane & 7) * 144 + ((lane >> 3) & 1) * 16 + (lane >> 4) * 8 * 144);
    const uint32_t laneA68 = (uint32_t)(((lane & 7) + ((lane >> 3) & 1) * 8) * 272 + (lane >> 4) * 16);
    const uint32_t laneB68 = (uint32_t)((lane & 7) * 272 + ((lane >> 3) & 1) * 16 + (lane >> 4) * 8 * 272);
    const uint32_t qbase = smbase + FQ2 * 4 + (uint32_t)(wr0) * 144 + laneA36;
    const uint32_t kbase = smbase + FK2 * 4 + laneB36;
    const uint32_t vbase = smbase + FV2 * 4 + laneB68;
    const uint32_t pbase = smbase + (FP2 + warp * 1088) * 4 + laneA68;

    #pragma unroll
    for (int i = 0; i < 4; i++) {
        int f = tid + (i << 8);
        int r = f >> 3, c16 = f & 7;
        uint4 q4 = *(const uint4*)(Q + ((size_t)(t0 + r) * BB + bb) * qs + h * HDD + c16 * 8);
        *(uint4*)&Qs[r * 36 + c16 * 4] = q4;
    }

    float mA = -1e30f, mB = -1e30f, lA = 0.f, lB = 0.f;
    float o[8][4];
    #pragma unroll
    for (int nt = 0; nt < 8; nt++)
        #pragma unroll
        for (int i = 0; i < 4; i++) o[nt][i] = 0.f;

    const int n_stiles = causal ? (tb + 1) : (SSZ / 128);

    for (int is = 0; is < n_stiles; is++) {
        int s0 = is * 128;
        __syncthreads();

        #pragma unroll
        for (int i = 0; i < 4; i++) {
            int f = tid + (i << 8);
            int r = f >> 3, c16 = f & 7;
            uint4 k4 = *(const uint4*)(Kk + ((size_t)(s0 + r) * BB + bb) * ks_ + h * HDD + c16 * 8);
            *(uint4*)&Ks[r * 36 + c16 * 4] = k4;
        }
        #pragma unroll
        for (int i = 0; i < 2; i++) {
            int f = tid + (i << 8);
            int s2 = f & 63;
            int hg = f >> 6;
            const __half* vr0 = V + ((size_t)(s0 + 2 * s2) * BB + bb) * vs + h * HDD + hg * 8;
            const __half* vr1 = vr0 + (size_t)BB * vs;
            uint4 a4 = *(const uint4*)vr0;
            uint4 b4 = *(const uint4*)vr1;
            const __half* ap = (const __half*)&a4;
            const __half* bp = (const __half*)&b4;
            #pragma unroll
            for (int j = 0; j < 8; j++) {
                __half2 w = __halves2half2(ap[j], bp[j]);
                Vs[(hg * 8 + j) * 68 + s2] = *(uint32_t*)&w;
            }
        }
        __syncthreads();

        float s[16][4];
        #pragma unroll
        for (int nt = 0; nt < 16; nt++)
            #pragma unroll
            for (int i = 0; i < 4; i++) s[nt][i] = 0.f;

        #pragma unroll
        for (int ks = 0; ks < 4; ks++) {
            uint32_t kof = ks * 32;
            uint32_t af[4];
            ldsm_x4(af[0], af[1], af[2], af[3], qbase + kof);
            #pragma unroll
            for (int ntp = 0; ntp < 8; ntp++) {
                uint32_t b00, b01, b10, b11;
                ldsm_x4(b00, b01, b10, b11, kbase + (uint32_t)(ntp * 16) * 144 + kof);
                mma_fp16(s[2 * ntp],     af, b00, b01);
                mma_fp16(s[2 * ntp + 1], af, b10, b11);
            }
        }

        const float scale = 0.125f;
        if (causal && is == tb) {
            int tAr = t0 + wr0 + g, tBr = tAr + 8;
            #pragma unroll
            for (int nt = 0; nt < 16; nt++) {
                int c = s0 + nt * 8 + tig * 2;
                s[nt][0] = s[nt][0] * scale + mask[(size_t)tAr * TT + c];
                s[nt][1] = s[nt][1] * scale + mask[(size_t)tAr * TT + c + 1];
                s[nt][2] = s[nt][2] * scale + mask[(size_t)tBr * TT + c];
                s[nt][3] = s[nt][3] * scale + mask[(size_t)tBr * TT + c + 1];
            }
        } else {
            #pragma unroll
            for (int nt = 0; nt < 16; nt++)
                #pragma unroll
                for (int i = 0; i < 4; i++) s[nt][i] *= scale;
        }

        float mtA = -1e30f, mtB = -1e30f;
        #pragma unroll
        for (int nt = 0; nt < 16; nt++) {
            mtA = fmaxf(mtA, fmaxf(s[nt][0], s[nt][1]));
            mtB = fmaxf(mtB, fmaxf(s[nt][2], s[nt][3]));
        }
        mtA = fmaxf(mtA, __shfl_xor_sync(0xffffffffu, mtA, 1));
        mtA = fmaxf(mtA, __shfl_xor_sync(0xffffffffu, mtA, 2));
        mtB = fmaxf(mtB, __shfl_xor_sync(0xffffffffu, mtB, 1));
        mtB = fmaxf(mtB, __shfl_xor_sync(0xffffffffu, mtB, 2));

        float mnA = fmaxf(mA, mtA), mnB = fmaxf(mB, mtB);
        float alA = __expf(mA - mnA), alB = __expf(mB - mnB);
        float rsA = 0.f, rsB = 0.f;
        #pragma unroll
        for (int nt = 0; nt < 16; nt++) {
            s[nt][0] = __expf(s[nt][0] - mnA);
            s[nt][1] = __expf(s[nt][1] - mnA);
            s[nt][2] = __expf(s[nt][2] - mnB);
            s[nt][3] = __expf(s[nt][3] - mnB);
            rsA += s[nt][0] + s[nt][1];
            rsB += s[nt][2] + s[nt][3];
        }
        rsA += __shfl_xor_sync(0xffffffffu, rsA, 1);
        rsA += __shfl_xor_sync(0xffffffffu, rsA, 2);
        rsB += __shfl_xor_sync(0xffffffffu, rsB, 1);
        rsB += __shfl_xor_sync(0xffffffffu, rsB, 2);
        lA = lA * alA + rsA; mA = mnA;
        lB = lB * alB + rsB; mB = mnB;

        #pragma unroll
        for (int nt = 0; nt < 8; nt++) {
            o[nt][0] *= alA; o[nt][1] *= alA;
            o[nt][2] *= alB; o[nt][3] *= alB;
        }

        __syncwarp();
        #pragma unroll
        for (int nt = 0; nt < 16; nt++) {
            __half2 wA = __floats2half2_rn(s[nt][0], s[nt][1]);
            __half2 wB = __floats2half2_rn(s[nt][2], s[nt][3]);
            Pw[g * 68 + nt * 4 + tig]       = *(uint32_t*)&wA;
            Pw[(g + 8) * 68 + nt * 4 + tig] = *(uint32_t*)&wB;
        }
        __syncwarp();

        #pragma unroll
        for (int ks = 0; ks < 8; ks++) {
            uint32_t kof = ks * 32;
            uint32_t af[4];
            ldsm_x4(af[0], af[1], af[2], af[3], pbase + kof);
            #pragma unroll
            for (int ntp = 0; ntp < 4; ntp++) {
                uint32_t b00, b01, b10, b11;
                ldsm_x4(b00, b01, b10, b11, vbase + (uint32_t)(ntp * 16) * 272 + kof);
                mma_fp16(o[2 * ntp],     af, b00, b01);
                mma_fp16(o[2 * ntp + 1], af, b10, b11);
            }
        }
    }

    float invA = 1.f / lA, invB = 1.f / lB;
    int tA = t0 + wr0 + g, tB = tA + 8;
    #pragma unroll
    for (int nt = 0; nt < 8; nt++) {
        int hd = nt * 8 + tig * 2;
        float a0 = o[nt][0] * invA, a1 = o[nt][1] * invA;
        float b0 = o[nt][2] * invB, b1 = o[nt][3] * invB;
        *(__half2*)(ctx_h + ((size_t)tA * BB + bb) * DD + h * HDD + hd) = __floats2half2_rn(a0, a1);
        *(__half2*)(ctx_h + ((size_t)tB * BB + bb) * DD + h * HDD + hd) = __floats2half2_rn(b0, b1);
        if (attn) {
            *(float2*)(attn + (((size_t)h * BB + bb) * TT + tA) * HDD + hd) = make_float2(a0, a1);
            *(float2*)(attn + (((size_t)h * BB + bb) * TT + tB) * HDD + hd) = make_float2(b0, b1);
        }
    }
}

// ---------------- fused residual add + layernorm (optional fp16 dual store)
__global__ __launch_bounds__(256) void add_ln_kernel(
    const float* __restrict__ a, const float* __restrict__ r,
    const float* __restrict__ g, const float* __restrict__ be,
    float* __restrict__ o, __half* __restrict__ oh)
{
    size_t row = blockIdx.x;
    int tid = threadIdx.x;
    float4 va = *(const float4*)(a + row * DD + tid * 4);
    float4 vr = *(const float4*)(r + row * DD + tid * 4);
    float x0 = va.x + vr.x, x1 = va.y + vr.y, x2 = va.z + vr.z, x3 = va.w + vr.w;
    float s  = block_sum(x0 + x1 + x2 + x3);
    float mu = s * (1.f / DD);
    float d0 = x0 - mu, d1 = x1 - mu, d2 = x2 - mu, d3 = x3 - mu;
    float sq = block_sum(d0 * d0 + d1 * d1 + d2 * d2 + d3 * d3);
    float inv = rsqrtf(sq * (1.f / DD) + 1e-5f);
    float4 vg = *(const float4*)(g + tid * 4);
    float4 vb = *(const float4*)(be + tid * 4);
    float4 out;
    out.x = d0 * inv * vg.x + vb.x;
    out.y = d1 * inv * vg.y + vb.y;
    out.z = d2 * inv * vg.z + vb.z;
    out.w = d3 * inv * vg.w + vb.w;
    *(float4*)(o + row * DD + tid * 4) = out;
    if (oh) {
        *(__half2*)(oh + row * DD + tid * 4)     = __floats2half2_rn(out.x, out.y);
        *(__half2*)(oh + row * DD + tid * 4 + 2) = __floats2half2_rn(out.z, out.w);
    }
}

// ---------------- host launch ----------------
extern "C" void kernel_launch(void* const* d_in, const int* in_sizes, int n_in,
                              void* d_out, int out_size)
{
    const float* state = (const float*)d_in[0];
    const float* enc   = (const float*)d_in[1];
    const float* amask = (const float*)d_in[2];
    const int* spad = (const int*)d_in[3];
    const int* epad = (const int*)d_in[4];
    const float *saWq = (const float*)d_in[5],  *sabq = (const float*)d_in[6];
    const float *saWk = (const float*)d_in[7],  *sabk = (const float*)d_in[8];
    const float *saWv = (const float*)d_in[9],  *sabv = (const float*)d_in[10];
    const float *saWo = (const float*)d_in[11], *sabo = (const float*)d_in[12];
    const float *eaWq = (const float*)d_in[13], *eabq = (const float*)d_in[14];
    const float *eaWk = (const float*)d_in[15], *eabk = (const float*)d_in[16];
    const float *eaWv = (const float*)d_in[17], *eabv = (const float*)d_in[18];
    const float *eaWo = (const float*)d_in[19], *eabo = (const float*)d_in[20];
    const float *ln1g = (const float*)d_in[21], *ln1b = (const float*)d_in[22];
    const float *ln2g = (const float*)d_in[23], *ln2b = (const float*)d_in[24];
    const float *ln3g = (const float*)d_in[25], *ln3b = (const float*)d_in[26];
    const float *fc1W = (const float*)d_in[27], *fc1b = (const float*)d_in[28];
    const float *fc2W = (const float*)d_in[29], *fc2b = (const float*)d_in[30];

    __half *state_h, *enc_h, *qkv_h, *kv_h, *q2_h, *ctx_h, *x1h, *x2h, *ffn_h, *wh;
    float *tmp, *x1, *x2, *rss, *rse;
    cudaGetSymbolAddress((void**)&state_h, g_state_h);
    cudaGetSymbolAddress((void**)&enc_h,   g_enc_h);
    cudaGetSymbolAddress((void**)&qkv_h, g_qkv_h);
    cudaGetSymbolAddress((void**)&kv_h,  g_kv_h);
    cudaGetSymbolAddress((void**)&q2_h,  g_q2_h);
    cudaGetSymbolAddress((void**)&ctx_h, g_ctx_h);
    cudaGetSymbolAddress((void**)&tmp, g_tmp);
    cudaGetSymbolAddress((void**)&x1,  g_x1);
    cudaGetSymbolAddress((void**)&x1h, g_x1h);
    cudaGetSymbolAddress((void**)&x2,  g_x2);
    cudaGetSymbolAddress((void**)&x2h, g_x2h);
    cudaGetSymbolAddress((void**)&ffn_h, g_ffn_h);
    cudaGetSymbolAddress((void**)&rss, g_rs_self);
    cudaGetSymbolAddress((void**)&rse, g_rs_enc);
    cudaGetSymbolAddress((void**)&wh,  g_wh);

    const int FSM = FL2_WORDS * 4;
    cudaFuncSetAttribute(gemm_fp16_kernel,  cudaFuncAttributeMaxDynamicSharedMemorySize, GSMB);
    cudaFuncSetAttribute(flash_fp16_kernel, cudaFuncAttributeMaxDynamicSharedMemorySize, FSM);

    float* outx = (float*)d_out;
    float* outa = outx + (size_t)MM * DD;

    const int NW = DD * DD;
    const int NF = FFND * DD;
    const int NA = MM * DD;
    CvtJobs jobs;
    jobs.src[0] = saWq; jobs.dst[0] = wh + WOFF_SAQ; jobs.n[0] = NW;
    jobs.src[1] = saWk; jobs.dst[1] = wh + WOFF_SAK; jobs.n[1] = NW;
    jobs.src[2] = saWv; jobs.dst[2] = wh + WOFF_SAV; jobs.n[2] = NW;
    jobs.src[3] = saWo; jobs.dst[3] = wh + WOFF_SAO; jobs.n[3] = NW;
    jobs.src[4] = eaWq; jobs.dst[4] = wh + WOFF_EAQ; jobs.n[4] = NW;
    jobs.src[5] = eaWk; jobs.dst[5] = wh + WOFF_EAK; jobs.n[5] = NW;
    jobs.src[6] = eaWv; jobs.dst[6] = wh + WOFF_EAV; jobs.n[6] = NW;
    jobs.src[7] = eaWo; jobs.dst[7] = wh + WOFF_EAO; jobs.n[7] = NW;
    jobs.src[8] = fc1W; jobs.dst[8] = wh + WOFF_FC1; jobs.n[8] = NF;
    jobs.src[9] = fc2W; jobs.dst[9] = wh + WOFF_FC2; jobs.n[9] = NF;
    jobs.src[10] = state; jobs.dst[10] = state_h; jobs.n[10] = NA;
    jobs.src[11] = enc;   jobs.dst[11] = enc_h;   jobs.n[11] = NA;
    cvt_all_kernel<<<dim3(NF / 1024, 12), 256>>>(jobs);

    expand_mask_kernel<<<(MM + 255) / 256, 256>>>(spad, rss, TT);
    expand_mask_kernel<<<(MM + 255) / 256, 256>>>(epad, rse, SSZ);

    dim3 gQKV(3 * DD / 128, MM / 256);   // (24,16)
    dim3 gKV(2 * DD / 128, MM / 256);    // (16,16)
    dim3 gP(DD / 128, MM / 256);         // (8,16)
    dim3 gF1(FFND / 128, MM / 256);      // (32,16)
    dim3 gFl(TT / 128, BB * HH);

    BiasSet bQKV = {{sabq, sabk, sabv, sabv}};
    BiasSet bKV  = {{eabk, eabv, eabv, eabv}};
    BiasSet bSAO = {{sabo, sabo, sabo, sabo}};
    BiasSet bEAQ = {{eabq, eabq, eabq, eabq}};
    BiasSet bEAO = {{eabo, eabo, eabo, eabo}};
    BiasSet bFC1 = {{fc1b, fc1b + 1024, fc1b + 2048, fc1b + 3072}};
    BiasSet bFC2 = {{fc2b, fc2b, fc2b, fc2b}};

    // ---- self-attention ----
    gemm_fp16_kernel<<<gQKV, 256, GSMB>>>(state_h, wh + WOFF_SAQ, bQKV, rss, 1,
                                          nullptr, qkv_h, MM, 3 * DD, DD, 0);
    flash_fp16_kernel<<<gFl, 256, FSM>>>(qkv_h, 3 * DD, qkv_h + DD, 3 * DD, qkv_h + 2 * DD, 3 * DD,
                                         amask, ctx_h, nullptr, 1);
    gemm_fp16_kernel<<<gP, 256, GSMB>>>(ctx_h, wh + WOFF_SAO, bSAO, nullptr, -1,
                                        tmp, nullptr, MM, DD, DD, 0);
    add_ln_kernel<<<MM, 256>>>(tmp, state, ln1g, ln1b, x1, x1h);

    // ---- encoder-decoder attention ----
    gemm_fp16_kernel<<<gP, 256, GSMB>>>(x1h, wh + WOFF_EAQ, bEAQ, nullptr, -1,
                                        nullptr, q2_h, MM, DD, DD, 0);
    gemm_fp16_kernel<<<gKV, 256, GSMB>>>(enc_h, wh + WOFF_EAK, bKV, rse, 0,
                                         nullptr, kv_h, MM, 2 * DD, DD, 0);
    flash_fp16_kernel<<<gFl, 256, FSM>>>(q2_h, DD, kv_h, 2 * DD, kv_h + DD, 2 * DD,
                                         nullptr, ctx_h, outa, 0);
    gemm_fp16_kernel<<<gP, 256, GSMB>>>(ctx_h, wh + WOFF_EAO, bEAO, nullptr, -1,
                                        tmp, nullptr, MM, DD, DD, 0);
    add_ln_kernel<<<MM, 256>>>(tmp, x1, ln2g, ln2b, x2, x2h);

    // ---- FFN ----
    gemm_fp16_kernel<<<gF1, 256, GSMB>>>(x2h, wh + WOFF_FC1, bFC1, nullptr, -1,
                                         nullptr, ffn_h, MM, FFND, DD, 1);
    gemm_fp16_kernel<<<gP, 256, GSMB>>>(ffn_h, wh + WOFF_FC2, bFC2, nullptr, -1,
                                        tmp, nullptr, MM, DD, FFND, 0);
    add_ln_kernel<<<MM, 256>>>(tmp, x2, ln3g, ln3b, outx, nullptr);
}